// round 8
// baseline (speedup 1.0000x reference)
#include <cuda_runtime.h>
#include <cstdint>

// S5 SSM scan, B-folded form:
//   x'_t = Atilde * x'_{t-1} + u_t      (input is the FMA addend)
//   y_t  = sum_n (C*Btilde)_n * x'_{t,n}
// batch=32, L=4096, D=256, N=64, fp32.
//
// Execution shape: 1024 single-warp CTAs. Each CTA owns 8 d-channels of one
// batch row; 4 threads per channel, 16 states (8 f32x2 pairs) each, all
// coefficients/state in registers. Per-step y-partials go to smem via STS.64;
// every 16 steps the warp reduces them and writes out coalesced (8 consecutive
// d per lane group). No shfl, no __syncthreads in the hot path.
// u double-buffered in smem via cp.async (2KB tiles of 64 timesteps).

#define SEQ    4096
#define DMODEL 256
#define DSTATE 64
#define TT     64      // timesteps per smem tile
#define DGC    8       // d-channels per CTA
#define NTH    32      // threads per CTA (one warp)
#define JH     8       // f32x2 pairs per thread (16 states)

typedef unsigned long long u64;

__device__ __forceinline__ u64 pack2(float lo, float hi) {
    u64 r; asm("mov.b64 %0, {%1,%2};" : "=l"(r) : "f"(lo), "f"(hi)); return r;
}
__device__ __forceinline__ float2 unpack2(u64 v) {
    float2 f; asm("mov.b64 {%0,%1}, %2;" : "=f"(f.x), "=f"(f.y) : "l"(v)); return f;
}
__device__ __forceinline__ u64 fma2(u64 a, u64 b, u64 c) {
    u64 d; asm("fma.rn.f32x2 %0, %1, %2, %3;" : "=l"(d) : "l"(a), "l"(b), "l"(c)); return d;
}
__device__ __forceinline__ u64 mul2(u64 a, u64 b) {
    u64 d; asm("mul.rn.f32x2 %0, %1, %2;" : "=l"(d) : "l"(a), "l"(b)); return d;
}
__device__ __forceinline__ u64 add2(u64 a, u64 b) {
    u64 d; asm("add.rn.f32x2 %0, %1, %2;" : "=l"(d) : "l"(a), "l"(b)); return d;
}

__global__ __launch_bounds__(NTH, 7)
void s5_scan_kernel(const float* __restrict__ u,
                    const float* __restrict__ log_dt,
                    const float* __restrict__ A_real,
                    const float* __restrict__ Bm,
                    const float* __restrict__ Cm,
                    const float* __restrict__ x0,
                    float* __restrict__ out)
{
    __shared__ float us[2][TT][DGC];                      // 2 x 2KB
    __shared__ __align__(16) u64 ys[16][DGC][4];          // 4KB partials

    const int tid = threadIdx.x;
    const int c   = tid >> 2;              // channel within CTA (0..7)
    const int h   = tid & 3;               // state quarter (16 states)
    const int b   = blockIdx.x >> 5;       // batch (0..31)
    const int g   = blockIdx.x & 31;       // d-group (0..31)
    const int d0  = g * DGC;
    const int d   = d0 + c;

    // ---- init: discretize + fold Btilde into C ----
    u64 A2[JH], C2[JH], X2[JH];
    {
        const float dt = expf(log_dt[d]);   // DT_SCALE = 1.0
        const int base = d * DSTATE + h * 16;
        #pragma unroll
        for (int j = 0; j < JH; j++) {
            const float ar0 = A_real[base + 2*j];
            const float ar1 = A_real[base + 2*j + 1];
            const float at0 = expf(ar0 * dt);
            const float at1 = expf(ar1 * dt);
            const float bt0 = (1.0f - at0) * Bm[base + 2*j]     / ar0;
            const float bt1 = (1.0f - at1) * Bm[base + 2*j + 1] / ar1;
            A2[j] = pack2(at0, at1);
            C2[j] = pack2(Cm[base + 2*j] * bt0, Cm[base + 2*j + 1] * bt1);
            const float xv0 = x0[base + 2*j];
            const float xv1 = x0[base + 2*j + 1];
            const float xp0 = (bt0 != 0.0f) ? (xv0 / bt0) : 0.0f;
            const float xp1 = (bt1 != 0.0f) ? (xv1 / bt1) : 0.0f;
            X2[j] = pack2(xp0, xp1);
        }
    }

    // ---- u tile prefetch (cp.async, 16B granules; 2KB per tile) ----
    const uint32_t sb0 = (uint32_t)__cvta_generic_to_shared(&us[0][0][0]);
    const uint32_t sb1 = (uint32_t)__cvta_generic_to_shared(&us[1][0][0]);
    const float* gbase = u + ((size_t)b * SEQ) * DMODEL + d0;

    auto load_tile = [&](int t0, int s) {
        const uint32_t sbase = s ? sb1 : sb0;
        #pragma unroll
        for (int k = 0; k < 4; k++) {
            const int idx  = tid + k * NTH;          // 0..127 16B chunks
            const int row  = idx >> 1;               // timestep within tile
            const int half = idx & 1;                // which 16B of the 32B row
            const float* gp = gbase + (size_t)(t0 + row) * DMODEL + half * 4;
            const uint32_t sa = sbase + (uint32_t)((row * DGC + half * 4) * 4);
            asm volatile("cp.async.cg.shared.global [%0], [%1], 16;" :: "r"(sa), "l"(gp));
        }
        asm volatile("cp.async.commit_group;" ::: "memory");
    };

    const int NT = SEQ / TT;   // 64 tiles
    load_tile(0, 0);

    for (int tile = 0; tile < NT; ++tile) {
        const int cur = tile & 1;
        asm volatile("cp.async.wait_group 0;" ::: "memory");
        __syncwarp();
        if (tile + 1 < NT) load_tile((tile + 1) * TT, cur ^ 1);

        const float* up = &us[cur][0][c];
        const size_t obase = (size_t)b * SEQ * DMODEL + (size_t)tile * TT * DMODEL + d0;

        #pragma unroll 1
        for (int blk = 0; blk < 4; ++blk) {        // 4 x 16 steps
            #pragma unroll
            for (int q = 0; q < 4; ++q) {          // 4 x 4 steps
                const int tb = blk * 16 + q * 4;
                const float uv0 = up[(tb + 0) * DGC];
                const float uv1 = up[(tb + 1) * DGC];
                const float uv2 = up[(tb + 2) * DGC];
                const float uv3 = up[(tb + 3) * DGC];
                const u64 ubv[4] = { pack2(uv0, uv0), pack2(uv1, uv1),
                                     pack2(uv2, uv2), pack2(uv3, uv3) };
                #pragma unroll
                for (int i = 0; i < 4; ++i) {
                    const u64 ub = ubv[i];
                    u64 ya, yb;
                    X2[0] = fma2(A2[0], X2[0], ub);  ya = mul2(C2[0], X2[0]);
                    X2[1] = fma2(A2[1], X2[1], ub);  yb = mul2(C2[1], X2[1]);
                    #pragma unroll
                    for (int j = 2; j < JH; j += 2) {
                        X2[j]   = fma2(A2[j],   X2[j],   ub);  ya = fma2(C2[j],   X2[j],   ya);
                        X2[j+1] = fma2(A2[j+1], X2[j+1], ub);  yb = fma2(C2[j+1], X2[j+1], yb);
                    }
                    ys[q * 4 + i][c][h] = add2(ya, yb);   // STS.64, fire-and-forget
                }
            }
            __syncwarp();

            // warp-local reduce of 16t x 8c partials + coalesced store
            #pragma unroll
            for (int k = 0; k < 4; ++k) {
                const int p  = tid + k * NTH;   // 0..127
                const int t  = p >> 3;          // 0..15
                const int cc = p & 7;           // 0..7
                const float4 v0 = *(const float4*)&ys[t][cc][0];
                const float4 v1 = *(const float4*)&ys[t][cc][2];
                const float s = ((v0.x + v0.y) + (v0.z + v0.w))
                              + ((v1.x + v1.y) + (v1.z + v1.w));
                out[obase + (size_t)(blk * 16 + t) * DMODEL + cc] = s;
            }
            __syncwarp();
        }
    }
}

extern "C" void kernel_launch(void* const* d_in, const int* in_sizes, int n_in,
                              void* d_out, int out_size)
{
    const float* u      = (const float*)d_in[0];
    const float* log_dt = (const float*)d_in[1];
    const float* A_real = (const float*)d_in[2];
    const float* B      = (const float*)d_in[3];
    const float* C      = (const float*)d_in[4];
    const float* x0     = (const float*)d_in[5];
    float* out = (float*)d_out;

    s5_scan_kernel<<<1024, NTH>>>(u, log_dt, A_real, B, C, x0, out);
}